// round 2
// baseline (speedup 1.0000x reference)
#include <cuda_runtime.h>
#include <math.h>

// Problem constants (fixed by setup_inputs)
#define EMAX 500000
#define NEMAX 100000
#define NRMAX 1008
#define DD 128
#define UU 128
#define KTOT 384

// ---------- device scratch (static; no allocation allowed) ----------
__device__ __align__(16) float g_wa[KTOT];       // W @ a
__device__ float g_p[NEMAX];                     // emb[n] . wa[0:128]
__device__ float g_q[NEMAX];                     // emb[n] . wa[256:384]
__device__ float g_s[NRMAX];                     // rel[r] . wa[128:256]
__device__ float g_score[EMAX];                  // score, then exp(score-m)
__device__ float g_m[NEMAX];                     // segment max
__device__ float g_denom[NEMAX];                 // segment sum of exp
__device__ float4 g_RT4[NEMAX * 64];             // [n][0:32]=alpha*r sum, [32:64]=alpha*t sum (float4 units)

// ---------- helpers ----------
__device__ __forceinline__ void atomicMaxFloat(float* addr, float v) {
    if (v >= 0.f) atomicMax((int*)addr, __float_as_int(v));
    else          atomicMin((unsigned int*)addr, __float_as_uint(v));
}

// ---------- kernels ----------
__global__ void k_wa(const float* __restrict__ W, const float* __restrict__ a) {
    int k = blockIdx.x * blockDim.x + threadIdx.x;
    if (k < KTOT) {
        const float* row = W + (size_t)k * UU;
        float s = 0.f;
        #pragma unroll 8
        for (int u = 0; u < UU; u++) s = fmaf(row[u], a[u], s);
        g_wa[k] = s;
    }
}

__global__ void k_init(int NE) {
    int i = blockIdx.x * blockDim.x + threadIdx.x;
    if (i < NE) { g_m[i] = -INFINITY; g_denom[i] = 0.f; }
    int total4 = NE * 64;
    float4 z = make_float4(0.f, 0.f, 0.f, 0.f);
    for (int j = i; j < total4; j += gridDim.x * blockDim.x) g_RT4[j] = z;
}

__global__ void k_entity_dots(const float* __restrict__ emb, int NE) {
    int w = (blockIdx.x * blockDim.x + threadIdx.x) >> 5;
    int lane = threadIdx.x & 31;
    if (w >= NE) return;
    float4 v   = ((const float4*)(emb + (size_t)w * DD))[lane];
    float4 wa0 = ((const float4*)g_wa)[lane];
    float4 wa2 = ((const float4*)(g_wa + 256))[lane];
    float p = v.x*wa0.x + v.y*wa0.y + v.z*wa0.z + v.w*wa0.w;
    float q = v.x*wa2.x + v.y*wa2.y + v.z*wa2.z + v.w*wa2.w;
    #pragma unroll
    for (int o = 16; o; o >>= 1) {
        p += __shfl_xor_sync(0xffffffffu, p, o);
        q += __shfl_xor_sync(0xffffffffu, q, o);
    }
    if (lane == 0) { g_p[w] = p; g_q[w] = q; }
}

__global__ void k_rel_dots(const float* __restrict__ rel, int NR) {
    int w = (blockIdx.x * blockDim.x + threadIdx.x) >> 5;
    int lane = threadIdx.x & 31;
    if (w >= NR) return;
    float4 v  = ((const float4*)(rel + (size_t)w * DD))[lane];
    float4 wa = ((const float4*)(g_wa + 128))[lane];
    float s = v.x*wa.x + v.y*wa.y + v.z*wa.z + v.w*wa.w;
    #pragma unroll
    for (int o = 16; o; o >>= 1) s += __shfl_xor_sync(0xffffffffu, s, o);
    if (lane == 0) g_s[w] = s;
}

__global__ void k_score(const int* __restrict__ h, const int* __restrict__ r,
                        const int* __restrict__ t, const float* __restrict__ ab, int E) {
    int e = blockIdx.x * blockDim.x + threadIdx.x;
    if (e >= E) return;
    int hn = h[e];
    float x = g_p[hn] + g_s[r[e]] + g_q[t[e]] + ab[0];
    // leaky(leaky(x)) with alpha=0.2: x>=0 -> x ; x<0 -> 0.04x
    float sc = x >= 0.f ? x : 0.04f * x;
    g_score[e] = sc;
    atomicMaxFloat(&g_m[hn], sc);
}

__global__ void k_exp(const int* __restrict__ h, int E) {
    int e = blockIdx.x * blockDim.x + threadIdx.x;
    if (e >= E) return;
    int hn = h[e];
    float ex = expf(g_score[e] - g_m[hn]);
    g_score[e] = ex;
    atomicAdd(&g_denom[hn], ex);
}

// one warp per edge: scatter alpha * rel[r] into RT[h][0:128], alpha * emb[t] into RT[h][128:256]
__global__ __launch_bounds__(256) void k_scatter(const int* __restrict__ h, const int* __restrict__ r,
                                                 const int* __restrict__ t,
                                                 const float* __restrict__ ent,
                                                 const float* __restrict__ rel, int E) {
    int e = (blockIdx.x * blockDim.x + threadIdx.x) >> 5;
    int lane = threadIdx.x & 31;
    if (e >= E) return;
    int hn = h[e], rn = r[e], tn = t[e];
    float alpha = g_score[e] / g_denom[hn];
    float4* dst = g_RT4 + (size_t)hn * 64;
    float4 rv = ((const float4*)(rel + (size_t)rn * DD))[lane];
    atomicAdd(dst + lane, make_float4(alpha*rv.x, alpha*rv.y, alpha*rv.z, alpha*rv.w));
    float4 tv = ((const float4*)(ent + (size_t)tn * DD))[lane];
    atomicAdd(dst + 32 + lane, make_float4(alpha*tv.x, alpha*tv.y, alpha*tv.z, alpha*tv.w));
}

// out[n,:] = relu( mask(n) * (emb[n]@W1 + R[n]@W2 + T[n]@W3) + bias )
#define GTM 64
#define GKC 32
__global__ __launch_bounds__(256) void k_gemm(const float* __restrict__ emb,
                                              const float* __restrict__ W,
                                              const float* __restrict__ bias,
                                              float* __restrict__ out, int NE) {
    __shared__ float sA[GKC][GTM + 1];
    __shared__ float sB[GKC][128];
    int t  = threadIdx.x;
    int tx = t & 31;    // column group: cols tx*4 .. tx*4+3
    int ty = t >> 5;    // row group: rows ty, ty+8, ..., ty+56
    int n0 = blockIdx.x * GTM;
    const float* gRT = (const float*)g_RT4;

    float acc[8][4];
    #pragma unroll
    for (int i = 0; i < 8; i++)
        #pragma unroll
        for (int j = 0; j < 4; j++) acc[i][j] = 0.f;

    #pragma unroll 1
    for (int kt = 0; kt < KTOT / GKC; kt++) {
        int k0 = kt * GKC;
        const float* src; int stride, koff;
        if (k0 < 128) { src = emb; stride = 128; koff = k0; }
        else          { src = gRT; stride = 256; koff = k0 - 128; }
        // load A tile: 64 rows x 32 k
        #pragma unroll
        for (int i = 0; i < 8; i++) {
            int idx = t + 256 * i;
            int row = idx >> 5;
            int kk  = idx & 31;
            int n = n0 + row;
            float v = 0.f;
            if (n < NE) v = src[(size_t)n * stride + koff + kk];
            sA[kk][row] = v;
        }
        // load B tile: 32 k x 128 u
        #pragma unroll
        for (int i = 0; i < 16; i++) {
            int idx = t + 256 * i;
            int u  = idx & 127;
            int kk = idx >> 7;
            sB[kk][u] = W[(size_t)(k0 + kk) * 128 + u];
        }
        __syncthreads();
        #pragma unroll
        for (int kk = 0; kk < GKC; kk++) {
            float4 b = *(const float4*)&sB[kk][tx * 4];
            #pragma unroll
            for (int i = 0; i < 8; i++) {
                float av = sA[kk][ty + 8 * i];
                acc[i][0] = fmaf(av, b.x, acc[i][0]);
                acc[i][1] = fmaf(av, b.y, acc[i][1]);
                acc[i][2] = fmaf(av, b.z, acc[i][2]);
                acc[i][3] = fmaf(av, b.w, acc[i][3]);
            }
        }
        __syncthreads();
    }

    float4 bv = *(const float4*)&bias[tx * 4];
    #pragma unroll
    for (int i = 0; i < 8; i++) {
        int n = n0 + ty + 8 * i;
        if (n < NE) {
            float mask = g_denom[n] > 0.f ? 1.f : 0.f;
            float4 o;
            o.x = fmaxf(fmaf(acc[i][0], mask, bv.x), 0.f);
            o.y = fmaxf(fmaf(acc[i][1], mask, bv.y), 0.f);
            o.z = fmaxf(fmaf(acc[i][2], mask, bv.z), 0.f);
            o.w = fmaxf(fmaf(acc[i][3], mask, bv.w), 0.f);
            *(float4*)&out[(size_t)n * 128 + tx * 4] = o;
        }
    }
}

extern "C" void kernel_launch(void* const* d_in, const int* in_sizes, int n_in,
                              void* d_out, int out_size) {
    const int*   h    = (const int*)d_in[0];
    const int*   r    = (const int*)d_in[1];
    const int*   t    = (const int*)d_in[2];
    const float* emb  = (const float*)d_in[3];
    const float* rel  = (const float*)d_in[4];
    const float* W    = (const float*)d_in[5];
    const float* a    = (const float*)d_in[6];
    const float* ab   = (const float*)d_in[7];
    const float* bias = (const float*)d_in[8];
    float* out = (float*)d_out;

    int E  = in_sizes[0];
    int NE = in_sizes[3] / DD;
    int NR = in_sizes[4] / DD;

    k_wa<<<2, 256>>>(W, a);
    k_init<<<(NE * 64 + 255) / 256, 256>>>(NE);
    k_entity_dots<<<(NE * 32 + 255) / 256, 256>>>(emb, NE);
    k_rel_dots<<<(NR * 32 + 255) / 256, 256>>>(rel, NR);
    k_score<<<(E + 255) / 256, 256>>>(h, r, t, ab, E);
    k_exp<<<(E + 255) / 256, 256>>>(h, E);
    k_scatter<<<(E * 32 + 255) / 256, 256>>>(h, r, t, emb, rel, E);
    k_gemm<<<(NE + GTM - 1) / GTM, 256>>>(emb, W, bias, out, NE);
}

// round 3
// speedup vs baseline: 2.0102x; 2.0102x over previous
#include <cuda_runtime.h>
#include <math.h>
#include <stdint.h>

// Problem constants (fixed by setup_inputs)
#define EMAX 500000
#define NEMAX 100000
#define NRMAX 1008
#define DD 128
#define KTOT 384

// ---------- device scratch (static; no allocation allowed) ----------
__device__ __align__(16) float g_wa[KTOT];        // W @ a
__device__ float g_p[NEMAX];                      // emb[n] . wa[0:128]
__device__ float g_q[NEMAX];                      // emb[n] . wa[256:384]
__device__ float g_s[NRMAX];                      // rel[r] . wa[128:256]
__device__ float g_score[EMAX];                   // score, then exp(score-m)
__device__ float g_m[NEMAX];                      // segment max
__device__ float g_denom[NEMAX];                  // segment sum of exp
__device__ __align__(16) float g_acc[NEMAX * DD];   // emb@W1, then += scatter
__device__ __align__(16) float g_embW3[NEMAX * DD]; // emb@W3
__device__ __align__(16) float g_relW2[NRMAX * DD]; // rel@W2

// ---------- helpers ----------
__device__ __forceinline__ void atomicMaxFloat(float* addr, float v) {
    if (v >= 0.f) atomicMax((int*)addr, __float_as_int(v));
    else          atomicMin((unsigned int*)addr, __float_as_uint(v));
}

__device__ __forceinline__ uint32_t f2tf(float f) {
    uint32_t r;
    asm("cvt.rna.tf32.f32 %0, %1;" : "=r"(r) : "f"(f));
    return r;
}

// ---------- small kernels ----------
__global__ void k_wa(const float* __restrict__ W, const float* __restrict__ a) {
    int k = blockIdx.x * blockDim.x + threadIdx.x;
    if (k < KTOT) {
        const float* row = W + (size_t)k * DD;
        float s = 0.f;
        #pragma unroll 8
        for (int u = 0; u < DD; u++) s = fmaf(row[u], a[u], s);
        g_wa[k] = s;
    }
}

__global__ void k_init(int NE) {
    int i = blockIdx.x * blockDim.x + threadIdx.x;
    if (i < NE) { g_m[i] = -INFINITY; g_denom[i] = 0.f; }
}

__global__ void k_entity_dots(const float* __restrict__ emb, int NE) {
    int w = (blockIdx.x * blockDim.x + threadIdx.x) >> 5;
    int lane = threadIdx.x & 31;
    if (w >= NE) return;
    float4 v   = ((const float4*)(emb + (size_t)w * DD))[lane];
    float4 wa0 = ((const float4*)g_wa)[lane];
    float4 wa2 = ((const float4*)(g_wa + 256))[lane];
    float p = v.x*wa0.x + v.y*wa0.y + v.z*wa0.z + v.w*wa0.w;
    float q = v.x*wa2.x + v.y*wa2.y + v.z*wa2.z + v.w*wa2.w;
    #pragma unroll
    for (int o = 16; o; o >>= 1) {
        p += __shfl_xor_sync(0xffffffffu, p, o);
        q += __shfl_xor_sync(0xffffffffu, q, o);
    }
    if (lane == 0) { g_p[w] = p; g_q[w] = q; }
}

__global__ void k_rel_dots(const float* __restrict__ rel, int NR) {
    int w = (blockIdx.x * blockDim.x + threadIdx.x) >> 5;
    int lane = threadIdx.x & 31;
    if (w >= NR) return;
    float4 v  = ((const float4*)(rel + (size_t)w * DD))[lane];
    float4 wa = ((const float4*)(g_wa + 128))[lane];
    float s = v.x*wa.x + v.y*wa.y + v.z*wa.z + v.w*wa.w;
    #pragma unroll
    for (int o = 16; o; o >>= 1) s += __shfl_xor_sync(0xffffffffu, s, o);
    if (lane == 0) g_s[w] = s;
}

__global__ void k_score(const int* __restrict__ h, const int* __restrict__ r,
                        const int* __restrict__ t, const float* __restrict__ ab, int E) {
    int e = blockIdx.x * blockDim.x + threadIdx.x;
    if (e >= E) return;
    int hn = h[e];
    float x = g_p[hn] + g_s[r[e]] + g_q[t[e]] + ab[0];
    // leaky(leaky(x)) with alpha=0.2: x>=0 -> x ; x<0 -> 0.04x
    float sc = x >= 0.f ? x : 0.04f * x;
    g_score[e] = sc;
    atomicMaxFloat(&g_m[hn], sc);
}

__global__ void k_exp(const int* __restrict__ h, int E) {
    int e = blockIdx.x * blockDim.x + threadIdx.x;
    if (e >= E) return;
    int hn = h[e];
    float ex = expf(g_score[e] - g_m[hn]);
    g_score[e] = ex;
    atomicAdd(&g_denom[hn], ex);
}

// relW2[r][u] = rel[r] . W2[:,u]  (W rows 128..255)
__global__ void k_relW2(const float* __restrict__ rel, const float* __restrict__ W, int NR) {
    int rn = blockIdx.x;
    if (rn >= NR) return;
    int u = threadIdx.x;
    const float* rrow = rel + (size_t)rn * DD;
    float s = 0.f;
    #pragma unroll 8
    for (int k = 0; k < DD; k++) s = fmaf(rrow[k], W[(size_t)(128 + k) * DD + u], s);
    g_relW2[rn * DD + u] = s;
}

// ---------- tf32 tensor-core GEMM: [acc | embW3] = emb @ [W1 | W3] ----------
// C[NE,256] = A[NE,128] * B[128,256], B cols 0-127 from W rows 0-127 (W1),
// cols 128-255 from W rows 256-383 (W3). Block tile 64x256, 8 warps (2 M x 4 N),
// warp tile 32x64. K chunks of 32.
__global__ __launch_bounds__(256) void k_mm(const float* __restrict__ emb,
                                            const float* __restrict__ W, int NE) {
    __shared__ uint32_t As[64 * 36];   // [m][k], stride 36 -> conflict-free frag loads
    __shared__ uint32_t Bs[32 * 264];  // [k][u], stride 264 -> conflict-free frag loads
    int tid  = threadIdx.x;
    int lane = tid & 31;
    int wid  = tid >> 5;
    int g  = lane >> 2;   // groupID
    int t4 = lane & 3;    // threadID in group
    int wm = wid >> 2;    // 0-1
    int wn = wid & 3;     // 0-3
    int n0 = blockIdx.x * 64;

    float c[2][8][4];
    #pragma unroll
    for (int i = 0; i < 2; i++)
        #pragma unroll
        for (int j = 0; j < 8; j++)
            #pragma unroll
            for (int k = 0; k < 4; k++) c[i][j][k] = 0.f;

    #pragma unroll 1
    for (int kc = 0; kc < 4; kc++) {
        int k0 = kc * 32;
        // load A tile: 64 rows x 32 k
        #pragma unroll
        for (int i = 0; i < 2; i++) {
            int idx = tid + i * 256;       // 0..511
            int row = idx >> 3;            // 0..63
            int q   = idx & 7;             // float4 within 32-k chunk
            int n = n0 + row;
            float4 v = make_float4(0.f, 0.f, 0.f, 0.f);
            if (n < NE) v = *(const float4*)(emb + (size_t)n * DD + k0 + q * 4);
            *(uint4*)&As[row * 36 + q * 4] =
                make_uint4(f2tf(v.x), f2tf(v.y), f2tf(v.z), f2tf(v.w));
        }
        // load B tile: 32 k x 256 u
        #pragma unroll
        for (int i = 0; i < 8; i++) {
            int idx = tid + i * 256;       // 0..2047
            int k  = idx >> 6;             // 0..31
            int u  = (idx & 63) * 4;       // 0..252
            const float* src = (u < 128)
                ? (W + (size_t)(k0 + k) * DD + u)
                : (W + (size_t)(256 + k0 + k) * DD + (u - 128));
            float4 v = *(const float4*)src;
            *(uint4*)&Bs[k * 264 + u] =
                make_uint4(f2tf(v.x), f2tf(v.y), f2tf(v.z), f2tf(v.w));
        }
        __syncthreads();
        #pragma unroll
        for (int ks = 0; ks < 4; ks++) {
            int kk = ks * 8;
            uint32_t a[2][4], b[8][2];
            #pragma unroll
            for (int fm = 0; fm < 2; fm++) {
                int mr = wm * 32 + fm * 16 + g;
                a[fm][0] = As[mr * 36 + kk + t4];
                a[fm][1] = As[(mr + 8) * 36 + kk + t4];
                a[fm][2] = As[mr * 36 + kk + t4 + 4];
                a[fm][3] = As[(mr + 8) * 36 + kk + t4 + 4];
            }
            #pragma unroll
            for (int fn = 0; fn < 8; fn++) {
                int col = wn * 64 + fn * 8 + g;
                b[fn][0] = Bs[(kk + t4) * 264 + col];
                b[fn][1] = Bs[(kk + t4 + 4) * 264 + col];
            }
            #pragma unroll
            for (int fm = 0; fm < 2; fm++)
                #pragma unroll
                for (int fn = 0; fn < 8; fn++)
                    asm volatile(
                        "mma.sync.aligned.m16n8k8.row.col.f32.tf32.tf32.f32 "
                        "{%0,%1,%2,%3}, {%4,%5,%6,%7}, {%8,%9}, {%0,%1,%2,%3};"
                        : "+f"(c[fm][fn][0]), "+f"(c[fm][fn][1]),
                          "+f"(c[fm][fn][2]), "+f"(c[fm][fn][3])
                        : "r"(a[fm][0]), "r"(a[fm][1]), "r"(a[fm][2]), "r"(a[fm][3]),
                          "r"(b[fn][0]), "r"(b[fn][1]));
        }
        __syncthreads();
    }

    // store: warps wn 0,1 -> g_acc cols 0-127 ; wn 2,3 -> g_embW3 cols 0-127
    float* dstbase = (wn < 2) ? g_acc : g_embW3;
    int colbase = (wn < 2) ? wn * 64 : (wn - 2) * 64;
    #pragma unroll
    for (int fm = 0; fm < 2; fm++) {
        #pragma unroll
        for (int fn = 0; fn < 8; fn++) {
            int col = colbase + fn * 8 + t4 * 2;
            int r0 = n0 + wm * 32 + fm * 16 + g;
            if (r0 < NE)
                *(float2*)&dstbase[(size_t)r0 * DD + col] =
                    make_float2(c[fm][fn][0], c[fm][fn][1]);
            int r1 = r0 + 8;
            if (r1 < NE)
                *(float2*)&dstbase[(size_t)r1 * DD + col] =
                    make_float2(c[fm][fn][2], c[fm][fn][3]);
        }
    }
}

// one warp per edge: acc[h] += alpha * (relW2[r] + embW3[t])
__global__ __launch_bounds__(256) void k_scatter(const int* __restrict__ h,
                                                 const int* __restrict__ r,
                                                 const int* __restrict__ t, int E) {
    int e = (blockIdx.x * blockDim.x + threadIdx.x) >> 5;
    int lane = threadIdx.x & 31;
    if (e >= E) return;
    int hn = h[e], rn = r[e], tn = t[e];
    float alpha = g_score[e] / g_denom[hn];
    float4 rv = ((const float4*)g_relW2)[rn * 32 + lane];
    float4 tv = ((const float4*)g_embW3)[(size_t)tn * 32 + lane];
    float4* dst = ((float4*)g_acc) + (size_t)hn * 32 + lane;
    atomicAdd(dst, make_float4(alpha * (rv.x + tv.x), alpha * (rv.y + tv.y),
                               alpha * (rv.z + tv.z), alpha * (rv.w + tv.w)));
}

// out[n] = relu(mask(n) * acc[n] + bias)
__global__ void k_out(const float* __restrict__ bias, float* __restrict__ out, int NE) {
    int idx = blockIdx.x * blockDim.x + threadIdx.x;
    if (idx >= NE * 32) return;
    int n = idx >> 5, u4 = idx & 31;
    float m = g_denom[n] > 0.f ? 1.f : 0.f;
    float4 a = ((const float4*)g_acc)[idx];
    float4 b = ((const float4*)bias)[u4];
    float4 o;
    o.x = fmaxf(fmaf(a.x, m, b.x), 0.f);
    o.y = fmaxf(fmaf(a.y, m, b.y), 0.f);
    o.z = fmaxf(fmaf(a.z, m, b.z), 0.f);
    o.w = fmaxf(fmaf(a.w, m, b.w), 0.f);
    ((float4*)out)[idx] = o;
}

extern "C" void kernel_launch(void* const* d_in, const int* in_sizes, int n_in,
                              void* d_out, int out_size) {
    const int*   h    = (const int*)d_in[0];
    const int*   r    = (const int*)d_in[1];
    const int*   t    = (const int*)d_in[2];
    const float* emb  = (const float*)d_in[3];
    const float* rel  = (const float*)d_in[4];
    const float* W    = (const float*)d_in[5];
    const float* a    = (const float*)d_in[6];
    const float* ab   = (const float*)d_in[7];
    const float* bias = (const float*)d_in[8];
    float* out = (float*)d_out;

    int E  = in_sizes[0];
    int NE = in_sizes[3] / DD;
    int NR = in_sizes[4] / DD;

    k_wa<<<2, 256>>>(W, a);
    k_init<<<(NE + 255) / 256, 256>>>(NE);
    k_entity_dots<<<(NE * 32 + 255) / 256, 256>>>(emb, NE);
    k_rel_dots<<<(NR * 32 + 255) / 256, 256>>>(rel, NR);
    k_mm<<<(NE + 63) / 64, 256>>>(emb, W, NE);
    k_relW2<<<NR, 128>>>(rel, W, NR);
    k_score<<<(E + 255) / 256, 256>>>(h, r, t, ab, E);
    k_exp<<<(E + 255) / 256, 256>>>(h, E);
    k_scatter<<<(E * 32 + 255) / 256, 256>>>(h, r, t, E);
    k_out<<<(NE * 32 + 255) / 256, 256>>>(bias, out, NE);
}